// round 7
// baseline (speedup 1.0000x reference)
#include <cuda_runtime.h>
#include <float.h>

// fm [B=4, C=256, H=50, W=50] f32, rois [R=300,5] f32 -> out [R,256,7,7] f32.
#define PH 7
#define PW 7
#define B_ 4
#define C_ 256
#define H_ 50
#define W_ 50
#define HW (H_ * W_)

// channels-last scratch: fmT[b][y][x][c]  (10.24 MB, static device array)
__device__ float g_fmT[B_ * HW * C_];

__device__ __forceinline__ int clampi(int v, int lo, int hi) {
    return min(max(v, lo), hi);
}

// [256, 2500] -> [2500, 256] transpose per batch, 32x32 tiles. (validated R6)
__global__ __launch_bounds__(256) void transpose_kernel(
        const float* __restrict__ in) {
    __shared__ float tile[32][33];
    const int b   = blockIdx.z;
    const int hw0 = blockIdx.x * 32;
    const int c0  = blockIdx.y * 32;
    const int tx  = threadIdx.x;          // 32
    const int ty  = threadIdx.y;          // 8

    #pragma unroll
    for (int j = 0; j < 4; ++j) {
        int cl = ty + j * 8;
        int hw = hw0 + tx;
        if (hw < HW)
            tile[cl][tx] = in[(size_t)(b * C_ + c0 + cl) * HW + hw];
    }
    __syncthreads();
    #pragma unroll
    for (int j = 0; j < 4; ++j) {
        int hwl = ty + j * 8;
        int hw  = hw0 + hwl;
        if (hw < HW)
            g_fmT[(size_t)(b * HW + hw) * C_ + c0 + tx] = tile[tx][hwl];
    }
}

// Block = (ph, roi). Thread = float2 channel-pair (cp = 0..127).
// Warp load = 64 consecutive channels = 256B = 2 dense lines.
// pw sections fully unrolled with scalar bounds (no local memory);
// x unrolled x2 with dual accumulators for MLP >= 2.
__global__ __launch_bounds__(128) void roi_pool_kernel(
        const float* __restrict__ rois, float* __restrict__ out) {
    __shared__ float sm[PW][C_];           // [pw][c], 7 KB

    const int ph = blockIdx.x;
    const int r  = blockIdx.y;
    const int cp = threadIdx.x;            // channel pair index

    // ---- ROI box (block-uniform; jnp.round == rintf under RN) ----
    const float* rp = rois + r * 5;
    const int b  = (int)__ldg(rp + 4);                 // float truncation
    int x0 = clampi((int)rintf(__ldg(rp + 0)), 0, W_ - 1);
    int x1 = clampi((int)rintf(__ldg(rp + 2)), 0, W_ - 1);
    int y0 = clampi((int)rintf(__ldg(rp + 1)), 0, H_ - 1);
    int y1 = clampi((int)rintf(__ldg(rp + 3)), 0, H_ - 1);
    x1 = max(x1, x0 + 1);                  // edges may reach 50; reads <= 49
    y1 = max(y1, y0 + 1);
    const int w = x1 - x0;                 // 1..49
    const int h = y1 - y0;

    const int hs = y0 + (ph * h) / PH;
    const int he = y0 + ((ph + 1) * h + PH - 1) / PH;  // ceil

    const float* base = g_fmT + (size_t)b * HW * C_ + 2 * cp;

    #pragma unroll
    for (int pw = 0; pw < PW; ++pw) {
        const int ws = x0 + (pw * w) / PW;                     // scalar bounds
        const int we = x0 + ((pw + 1) * w + PW - 1) / PW;

        float2 ma = make_float2(-FLT_MAX, -FLT_MAX);
        float2 mb = make_float2(-FLT_MAX, -FLT_MAX);

        for (int y = hs; y < he; ++y) {
            const float* rowp = base + (size_t)(y * W_) * C_;
            int x = ws;
            for (; x + 1 < we; x += 2) {
                float2 a = __ldg((const float2*)(rowp + (size_t)x * C_));
                float2 c = __ldg((const float2*)(rowp + (size_t)(x + 1) * C_));
                ma.x = fmaxf(ma.x, a.x);  ma.y = fmaxf(ma.y, a.y);
                mb.x = fmaxf(mb.x, c.x);  mb.y = fmaxf(mb.y, c.y);
            }
            if (x < we) {
                float2 a = __ldg((const float2*)(rowp + (size_t)x * C_));
                ma.x = fmaxf(ma.x, a.x);  ma.y = fmaxf(ma.y, a.y);
            }
        }
        float2 m = make_float2(fmaxf(ma.x, mb.x), fmaxf(ma.y, mb.y));
        *(float2*)&sm[pw][2 * cp] = m;     // STS.64, conflict-free
    }
    __syncthreads();

    // staged stores: consecutive i -> ~5 lines per warp STG, cheap.
    float* ob = out + (size_t)r * (C_ * PH * PW) + ph * PW;
    #pragma unroll
    for (int i = cp; i < C_ * PW; i += 128) {
        int cc = i / PW;
        int pp = i - cc * PW;
        ob[cc * (PH * PW) + pp] = sm[pp][cc];
    }
}

extern "C" void kernel_launch(void* const* d_in, const int* in_sizes, int n_in,
                              void* d_out, int out_size) {
    const float* fm   = (const float*)d_in[0];
    const float* rois = (const float*)d_in[1];
    float* out = (float*)d_out;

    int R = in_sizes[1] / 5;               // 300

    dim3 tgrid((HW + 31) / 32, C_ / 32, B_);   // 79 x 8 x 4
    transpose_kernel<<<tgrid, dim3(32, 8)>>>(fm);

    dim3 pgrid(PH, R);                     // 7 x 300
    roi_pool_kernel<<<pgrid, 128>>>(rois, out);
}

// round 8
// speedup vs baseline: 1.6141x; 1.6141x over previous
#include <cuda_runtime.h>
#include <float.h>

// fm [B=4, C=256, H=50, W=50] f32, rois [R=300,5] f32 -> out [R,256,7,7] f32.
#define PH 7
#define PW 7
#define B_ 4
#define C_ 256
#define H_ 50
#define W_ 50
#define HW (H_ * W_)
#define R_MAX 512
#define BINS (PH * PW)                 // 49

// channels-last scratch: fmT[b][y][x][c]  (10.24 MB)
__device__ float g_fmT[B_ * HW * C_];
// channels-last output scratch: outT[r][bin][c]  (15.05 MB)
__device__ float g_outT[R_MAX * BINS * C_];

__device__ __forceinline__ int clampi(int v, int lo, int hi) {
    return min(max(v, lo), hi);
}

// [256, 2500] -> [2500, 256] transpose per batch, 32x32 tiles. (validated)
__global__ __launch_bounds__(256) void transpose_kernel(
        const float* __restrict__ in) {
    __shared__ float tile[32][33];
    const int b   = blockIdx.z;
    const int hw0 = blockIdx.x * 32;
    const int c0  = blockIdx.y * 32;
    const int tx  = threadIdx.x;          // 32
    const int ty  = threadIdx.y;          // 8

    #pragma unroll
    for (int j = 0; j < 4; ++j) {
        int cl = ty + j * 8;
        int hw = hw0 + tx;
        if (hw < HW)
            tile[cl][tx] = in[(size_t)(b * C_ + c0 + cl) * HW + hw];
    }
    __syncthreads();
    #pragma unroll
    for (int j = 0; j < 4; ++j) {
        int hwl = ty + j * 8;
        int hw  = hw0 + hwl;
        if (hw < HW)
            g_fmT[(size_t)(b * HW + hw) * C_ + c0 + tx] = tile[tx][hwl];
    }
}

// Block = (bin, roi): 14700 tiny uniform blocks. Thread = float2 channel-pair.
// Bin geometry block-uniform; ~12 independent float2 loads per thread,
// each warp-load = 64 consecutive channels = 2 dense 128B lines.
__global__ __launch_bounds__(128) void roi_pool_kernel(
        const float* __restrict__ rois) {
    const int bin = blockIdx.x;            // 0..48 (uniform in block)
    const int r   = blockIdx.y;
    const int cp  = threadIdx.x;           // channel pair 0..127

    // ---- ROI box (block-uniform; jnp.round == rintf under RN) ----
    const float* rp = rois + r * 5;
    const int b  = (int)__ldg(rp + 4);                 // float truncation
    int x0 = clampi((int)rintf(__ldg(rp + 0)), 0, W_ - 1);
    int x1 = clampi((int)rintf(__ldg(rp + 2)), 0, W_ - 1);
    int y0 = clampi((int)rintf(__ldg(rp + 1)), 0, H_ - 1);
    int y1 = clampi((int)rintf(__ldg(rp + 3)), 0, H_ - 1);
    x1 = max(x1, x0 + 1);                  // edges may reach 50; reads <= 49
    y1 = max(y1, y0 + 1);
    const int w = x1 - x0;                 // 1..49
    const int h = y1 - y0;

    const int ph = bin / PW;
    const int pw = bin - ph * PW;
    const int hs = y0 + (ph * h) / PH;
    const int he = y0 + ((ph + 1) * h + PH - 1) / PH;  // ceil
    const int ws = x0 + (pw * w) / PW;
    const int we = x0 + ((pw + 1) * w + PW - 1) / PW;
    const int bw = we - ws;                // 1..8

    const float* base = g_fmT + ((size_t)b * HW + ws) * C_ + 2 * cp;

    float2 ma = make_float2(-FLT_MAX, -FLT_MAX);
    float2 mb = make_float2(-FLT_MAX, -FLT_MAX);

    for (int y = hs; y < he; ++y) {
        const float* rowp = base + (size_t)(y * W_) * C_;
        int x = 0;
        for (; x + 1 < bw; x += 2) {
            float2 a = __ldg((const float2*)(rowp + (size_t)x * C_));
            float2 c = __ldg((const float2*)(rowp + (size_t)(x + 1) * C_));
            ma.x = fmaxf(ma.x, a.x);  ma.y = fmaxf(ma.y, a.y);
            mb.x = fmaxf(mb.x, c.x);  mb.y = fmaxf(mb.y, c.y);
        }
        if (x < bw) {
            float2 a = __ldg((const float2*)(rowp + (size_t)x * C_));
            ma.x = fmaxf(ma.x, a.x);  ma.y = fmaxf(ma.y, a.y);
        }
    }
    float2 m = make_float2(fmaxf(ma.x, mb.x), fmaxf(ma.y, mb.y));

    // dense store: warp writes 256 consecutive bytes
    *(float2*)&g_outT[((size_t)r * BINS + bin) * C_ + 2 * cp] = m;
}

// outT[r][49][256] -> out[r][256][49], 128-channel chunks via smem tile.
// Pitch 129: both phases bank-conflict-free.
__global__ __launch_bounds__(256) void reorder_kernel(float* __restrict__ out) {
    __shared__ float sm[BINS][129];
    const int r    = blockIdx.y;
    const int c0   = blockIdx.x * 128;     // 0 or 128
    const int tid  = threadIdx.x;

    const float* src = g_outT + (size_t)r * BINS * C_ + c0;
    for (int i = tid; i < BINS * 128; i += 256) {
        int bin = i >> 7;
        int c   = i & 127;
        sm[bin][c] = src[(size_t)bin * C_ + c];    // 512B coalesced runs
    }
    __syncthreads();

    float* dst = out + ((size_t)r * C_ + c0) * BINS;
    for (int i = tid; i < 128 * BINS; i += 256) {  // i = c*49 + bin
        int c   = i / BINS;
        int bin = i - c * BINS;
        dst[i] = sm[bin][c];                       // fully coalesced writes
    }
}

extern "C" void kernel_launch(void* const* d_in, const int* in_sizes, int n_in,
                              void* d_out, int out_size) {
    const float* fm   = (const float*)d_in[0];
    const float* rois = (const float*)d_in[1];
    float* out = (float*)d_out;

    int R = in_sizes[1] / 5;               // 300

    dim3 tgrid((HW + 31) / 32, C_ / 32, B_);   // 79 x 8 x 4
    transpose_kernel<<<tgrid, dim3(32, 8)>>>(fm);

    dim3 pgrid(BINS, R);                   // 49 x 300
    roi_pool_kernel<<<pgrid, 128>>>(rois);

    dim3 rgrid(2, R);                      // 2 x 300
    reorder_kernel<<<rgrid, 256>>>(out);
}